// round 14
// baseline (speedup 1.0000x reference)
#include <cuda_runtime.h>
#include <cuda_bf16.h>
#include <cstdint>

#define IMG 1024
#define EMBED 2700
#define ECH 50            // sim e-chunk (54 chunks * 50 = 2700)
#define NCH 54

// device scratch (no cudaMalloc allowed)
__device__ float d_boxes_px[2 * 2 * 100 * 4];   // [view][batch][slot][xyxy px]
__device__ float d_t [2 * 200 * EMBED];         // [view][row][e]
__device__ float d_gt[2 * 200 * EMBED];         // after Linear
__device__ float d_simp[NCH * 2 * 100 * 100];   // partial sims [ch][b][k][q]

// ---------- Stage 1: top-100 via histogram select + small bitonic ----------
__device__ __forceinline__ unsigned int prob_key(float x) {
    float p = 1.0f / (1.0f + expf(-x));
    return __float_as_uint(p);
}

__global__ void __launch_bounds__(1024) topk_kernel(
    const float* __restrict__ gl, const float* __restrict__ al,
    const float* __restrict__ gbx, const float* __restrict__ abx)
{
    int b = blockIdx.x, v = blockIdx.y;
    const float* logits = (v ? al : gl) + b * 6000;
    const float* boxes  = (v ? abx : gbx) + b * 300 * 4;
    int tid = threadIdx.x;

    __shared__ unsigned int hist[256];
    __shared__ int sT, scnt;
    __shared__ unsigned long long cand[4096];

    if (tid < 256) hist[tid] = 0u;
    __syncthreads();

    for (int i = tid; i < 6000; i += 1024)
        atomicAdd(&hist[prob_key(logits[i]) >> 22], 1u);
    __syncthreads();

    if (tid == 0) {
        unsigned int cum = 0; int T = 0;
        for (int bb = 255; bb >= 0; bb--) {
            cum += hist[bb];
            if (cum >= 100u) { T = bb; break; }
        }
        sT = T; scnt = 0;
    }
    __syncthreads();
    int T = sT;

    for (int i = tid; i < 6000; i += 1024) {
        unsigned int key = prob_key(logits[i]);
        if ((int)(key >> 22) >= T) {
            int pos = atomicAdd(&scnt, 1);
            if (pos < 4096)
                cand[pos] = (((unsigned long long)(0xFFFFFFFFu ^ key)) << 16)
                            | (unsigned long long)i;
        }
    }
    __syncthreads();

    int n = min(scnt, 4096);
    int n2 = 128;
    while (n2 < n) n2 <<= 1;

    for (int i = n + tid; i < n2; i += 1024) cand[i] = ~0ull;
    __syncthreads();

    for (int k = 2; k <= n2; k <<= 1)
        for (int j = k >> 1; j > 0; j >>= 1) {
            for (int i = tid; i < n2; i += 1024) {
                int ixj = i ^ j;
                if (ixj > i) {
                    unsigned long long a = cand[i], bb2 = cand[ixj];
                    bool up = ((i & k) == 0);
                    if ((a > bb2) == up) { cand[i] = bb2; cand[ixj] = a; }
                }
            }
            __syncthreads();
        }

    if (tid < 100) {
        int idx = (int)(cand[tid] & 0xFFFFull);
        int q = idx / 20;
        float cx = boxes[q*4+0], cy = boxes[q*4+1];
        float w  = boxes[q*4+2], h  = boxes[q*4+3];
        float* o = &d_boxes_px[((v*2 + b)*100 + tid)*4];
        o[0] = (cx - 0.5f*w) * 1024.0f;  o[1] = (cy - 0.5f*h) * 1024.0f;
        o[2] = (cx + 0.5f*w) * 1024.0f;  o[3] = (cy + 0.5f*h) * 1024.0f;
    }
}

// ---------- Stage 2: ROI bilinear 30x30 + interleave + pos_enc ----------
__global__ void __launch_bounds__(256) roi_kernel(
    const float* __restrict__ g_img, const float* __restrict__ a_img,
    const float* __restrict__ pos_enc)
{
    int m = blockIdx.x, v = blockIdx.y;
    const float* img = v ? a_img : g_img;
    int b = m & 1, kslot = m >> 1, k2 = m % 100;
    int tid = threadIdx.x;

    const float* bx = &d_boxes_px[((v*2 + b)*100 + kslot)*4];
    float x0 = rintf(bx[0]), y0 = rintf(bx[1]);
    float x1 = rintf(bx[2]), y1 = rintf(bx[3]);
    float w = x1 - x0, h = y1 - y0;
    bool valid = (w > 0.0f) && (h > 0.0f);

    __shared__ int   iy0[30], iy1[30], ix0[30], ix1[30];
    __shared__ float fwy[30], fwx[30];
    if (tid < 30) {
        float g = (float)tid + 0.5f;
        float sy = fminf(fmaxf(g * h / 30.0f - 0.5f, 0.0f), fmaxf(h - 1.0f, 0.0f));
        float ay = y0 + sy, yf = floorf(ay);
        fwy[tid] = ay - yf;
        iy0[tid] = (int)fminf(fmaxf(yf,        0.0f), 1023.0f);
        iy1[tid] = (int)fminf(fmaxf(yf + 1.0f, 0.0f), 1023.0f);
        float sx = fminf(fmaxf(g * w / 30.0f - 0.5f, 0.0f), fmaxf(w - 1.0f, 0.0f));
        float ax = x0 + sx, xf = floorf(ax);
        fwx[tid] = ax - xf;
        ix0[tid] = (int)fminf(fmaxf(xf,        0.0f), 1023.0f);
        ix1[tid] = (int)fminf(fmaxf(xf + 1.0f, 0.0f), 1023.0f);
    }
    __syncthreads();

    float* trow = &d_t[((size_t)(v*200 + m)) * EMBED];
    const float* pe = &pos_enc[(size_t)k2 * EMBED];
    for (int e = tid; e < EMBED; e += 256) {
        float val = 0.0f;
        if (valid) {
            int c = e / 900, r = e - c*900, py = r / 30, px = r - py*30;
            const float* ip = img + ((size_t)(b*3 + c) << 20);
            float wy = fwy[py], wx = fwx[px];
            const float* r0p = ip + iy0[py]*IMG;
            const float* r1p = ip + iy1[py]*IMG;
            float v00 = r0p[ix0[px]], v01 = r0p[ix1[px]];
            float v10 = r1p[ix0[px]], v11 = r1p[ix1[px]];
            float top = v00*(1.0f-wx) + v01*wx;
            float bot = v10*(1.0f-wx) + v11*wx;
            val = top*(1.0f-wy) + bot*wy;
        }
        trow[e] = val + pe[e];
    }
}

// ---------- Stage 3: gt = t @ W^T via mma.sync bf16 hi/lo split ----------
// BM=64, BN=64, 256 thr (8 warps 2x4; warp tile 32x16 -> 2040 MMA/warp).
// Grid 43x4x2 = 344 blocks; dynamic smem inflated to 77KB caps residency
// at 2 blocks/SM so completion-driven refill evens the SMSP MMA load.
#define KC 32
#define LDP 40   // padded row stride (bf16 elems): 80B -> conflict-free ldmatrix
#define TILE_BYTES (64 * LDP * 2)              // 5120 B per sub-array
#define SMEM_GEMM_REQ (77 * 1024)              // residency cap: 2 blocks/SM

__device__ __forceinline__ void ldm_x4(uint32_t& r0, uint32_t& r1, uint32_t& r2, uint32_t& r3,
                                       uint32_t addr) {
    asm volatile("ldmatrix.sync.aligned.m8n8.x4.shared.b16 {%0,%1,%2,%3}, [%4];"
                 : "=r"(r0), "=r"(r1), "=r"(r2), "=r"(r3) : "r"(addr));
}
__device__ __forceinline__ void ldm_x2(uint32_t& r0, uint32_t& r1, uint32_t addr) {
    asm volatile("ldmatrix.sync.aligned.m8n8.x2.shared.b16 {%0,%1}, [%2];"
                 : "=r"(r0), "=r"(r1) : "r"(addr));
}
__device__ __forceinline__ void mma_bf16(float* c, const uint32_t* a, const uint32_t* b) {
    asm volatile(
        "mma.sync.aligned.m16n8k16.row.col.f32.bf16.bf16.f32 "
        "{%0,%1,%2,%3}, {%4,%5,%6,%7}, {%8,%9}, {%0,%1,%2,%3};"
        : "+f"(c[0]), "+f"(c[1]), "+f"(c[2]), "+f"(c[3])
        : "r"(a[0]), "r"(a[1]), "r"(a[2]), "r"(a[3]), "r"(b[0]), "r"(b[1]));
}
__device__ __forceinline__ uint32_t smem_u32(const void* p) {
    uint32_t a;
    asm("{ .reg .u64 t; cvta.to.shared.u64 t, %1; cvt.u32.u64 %0, t; }" : "=r"(a) : "l"(p));
    return a;
}
__device__ __forceinline__ uint2 split4(float4 x) {
    __nv_bfloat16 h0 = __float2bfloat16(x.x), h1 = __float2bfloat16(x.y);
    __nv_bfloat16 h2 = __float2bfloat16(x.z), h3 = __float2bfloat16(x.w);
    __nv_bfloat162 a = __halves2bfloat162(h0, h1), b = __halves2bfloat162(h2, h3);
    return make_uint2(*(uint32_t*)&a, *(uint32_t*)&b);
}
__device__ __forceinline__ uint2 split4lo(float4 x) {
    __nv_bfloat16 h0 = __float2bfloat16(x.x), h1 = __float2bfloat16(x.y);
    __nv_bfloat16 h2 = __float2bfloat16(x.z), h3 = __float2bfloat16(x.w);
    __nv_bfloat16 l0 = __float2bfloat16(x.x - __bfloat162float(h0));
    __nv_bfloat16 l1 = __float2bfloat16(x.y - __bfloat162float(h1));
    __nv_bfloat16 l2 = __float2bfloat16(x.z - __bfloat162float(h2));
    __nv_bfloat16 l3 = __float2bfloat16(x.w - __bfloat162float(h3));
    __nv_bfloat162 a = __halves2bfloat162(l0, l1), b = __halves2bfloat162(l2, l3);
    return make_uint2(*(uint32_t*)&a, *(uint32_t*)&b);
}

__global__ void __launch_bounds__(256) hmma_gemm_kernel(
    const float* __restrict__ Wg, const float* __restrict__ Wa)
{
    extern __shared__ char smraw[];
    const int v = blockIdx.z;
    const int row0  = blockIdx.y * 64;
    const int ncol0 = blockIdx.x * 64;
    const float* __restrict__ A = d_t + (size_t)v * 200 * EMBED;
    const float* __restrict__ B = v ? Wa : Wg;
    float* __restrict__ C = d_gt + (size_t)v * 200 * EMBED;

    char* pAh = smraw;
    char* pAl = smraw + TILE_BYTES;
    char* pBh = smraw + 2 * TILE_BYTES;
    char* pBl = smraw + 3 * TILE_BYTES;

    int tid = threadIdx.x;
    int wid = tid >> 5, lane = tid & 31;
    int wm = wid >> 2, wn = wid & 3;          // 2x4 warp grid, warp tile 32x16

    bool imv0 = (row0 + wm * 32)      < 200;
    bool imv1 = (row0 + wm * 32 + 16) < 200;

    float acc[2][2][4];
#pragma unroll
    for (int i = 0; i < 2; i++)
#pragma unroll
        for (int j = 0; j < 2; j++)
#pragma unroll
            for (int p = 0; p < 4; p++) acc[i][j][p] = 0.0f;

    float4 aPre[2], bPre[2];

    auto loadTile = [&](int c) {
        int k0 = c * KC;
        // A: 64 rows x 32 cols = 512 float4 over 256 thr (2 each)
#pragma unroll
        for (int l = 0; l < 2; l++) {
            int g = tid + l * 256;
            int r = g >> 3, c4 = g & 7;
            int gr = row0 + r, gc = k0 + c4 * 4;
            float4 x = make_float4(0.f, 0.f, 0.f, 0.f);
            if (gr < 200 && gc < EMBED) x = *(const float4*)(A + (size_t)gr * EMBED + gc);
            aPre[l] = x;
            int gr2 = ncol0 + r;
            float4 y = make_float4(0.f, 0.f, 0.f, 0.f);
            if (gr2 < EMBED && gc < EMBED) y = *(const float4*)(B + (size_t)gr2 * EMBED + gc);
            bPre[l] = y;
        }
    };
    auto storeTile = [&]() {
#pragma unroll
        for (int l = 0; l < 2; l++) {
            int g = tid + l * 256;
            int r = g >> 3, c4 = g & 7;
            uint32_t off = (uint32_t)(r * LDP + c4 * 4) * 2;
            *(uint2*)(pAh + off) = split4(aPre[l]);
            *(uint2*)(pAl + off) = split4lo(aPre[l]);
            *(uint2*)(pBh + off) = split4(bPre[l]);
            *(uint2*)(pBl + off) = split4lo(bPre[l]);
        }
    };

    uint32_t sAh = smem_u32(pAh), sAl = smem_u32(pAl);
    uint32_t sBh = smem_u32(pBh), sBl = smem_u32(pBl);

    const int NCHK = (EMBED + KC - 1) / KC;   // 85
    loadTile(0); storeTile(); __syncthreads();

    for (int c = 0; c < NCHK; c++) {
        if (c + 1 < NCHK) loadTile(c + 1);

        if (imv0 || imv1) {
#pragma unroll
            for (int ks = 0; ks < 2; ks++) {
                int k0 = ks * 16;
                int sub = lane >> 3, ri = lane & 7;
                uint32_t ah[2][4], al[2][4], bh[2][2], bl[2][2];
#pragma unroll
                for (int jn = 0; jn < 2; jn++) {
                    int n0 = wn * 16 + jn * 8;
                    uint32_t off = ((uint32_t)((n0 + ri) * LDP + k0 + sub * 8)) * 2;
                    ldm_x2(bh[jn][0], bh[jn][1], sBh + off);
                    ldm_x2(bl[jn][0], bl[jn][1], sBl + off);
                }
#pragma unroll
                for (int im = 0; im < 2; im++) {
                    if (!(im ? imv1 : imv0)) continue;
                    int m0 = wm * 32 + im * 16;
                    uint32_t off = ((uint32_t)((m0 + (sub & 1) * 8 + ri) * LDP
                                               + k0 + (sub >> 1) * 8)) * 2;
                    ldm_x4(ah[im][0], ah[im][1], ah[im][2], ah[im][3], sAh + off);
                    ldm_x4(al[im][0], al[im][1], al[im][2], al[im][3], sAl + off);
#pragma unroll
                    for (int jn = 0; jn < 2; jn++) {
                        mma_bf16(acc[im][jn], ah[im], bh[jn]);
                        mma_bf16(acc[im][jn], ah[im], bl[jn]);
                        mma_bf16(acc[im][jn], al[im], bh[jn]);
                    }
                }
            }
        }
        __syncthreads();
        if (c + 1 < NCHK) { storeTile(); __syncthreads(); }
    }

#pragma unroll
    for (int im = 0; im < 2; im++) {
        if (!(im ? imv1 : imv0)) continue;
        int mbase = row0 + wm * 32 + im * 16 + (lane >> 2);
#pragma unroll
        for (int jn = 0; jn < 2; jn++) {
            int n = ncol0 + wn * 16 + jn * 8 + (lane & 3) * 2;
            if (n < EMBED) {
                if (mbase < 200)
                    *(float2*)(C + (size_t)mbase * EMBED + n) =
                        make_float2(acc[im][jn][0], acc[im][jn][1]);
                if (mbase + 8 < 200)
                    *(float2*)(C + (size_t)(mbase + 8) * EMBED + n) =
                        make_float2(acc[im][jn][2], acc[im][jn][3]);
            }
        }
    }
}

// ---------- Stage 4: sim partials, split over e-chunks ----------
// grid (NCH, 2), 512 threads. Thread grid 32(k) x 16(q), tile 7q x 4k.
__global__ void __launch_bounds__(512) sim_kernel()
{
    int ch = blockIdx.x, b2 = blockIdx.y;
    __shared__ float Gs [ECH][112];   // q-padded (indices <= 111 in-bounds)
    __shared__ float As2[ECH][129];   // k-padded (indices <= 127 in-bounds)

    int tid = threadIdx.x;
    int e0 = ch * ECH;
    for (int l = tid; l < 100 * ECH; l += 512) {
        int r = l / ECH, e = l - r * ECH;
        Gs [e][r] = d_gt[(size_t)(      b2*100 + r)*EMBED + e0 + e];
        As2[e][r] = d_gt[(size_t)(200 + b2*100 + r)*EMBED + e0 + e];
    }
    __syncthreads();

    int tx = tid & 31, ty = tid >> 5;        // tx: k, ty: q
    int nq = (ty < 4) ? 7 : 6;
    int nk = (tx < 4) ? 4 : 3;

    float acc[7][4];
#pragma unroll
    for (int i = 0; i < 7; i++)
#pragma unroll
        for (int j = 0; j < 4; j++) acc[i][j] = 0.0f;

    for (int e = 0; e < ECH; e++) {
        float ga[7], aa[4];
#pragma unroll
        for (int i = 0; i < 7; i++) ga[i] = Gs [e][ty + 16*i];
#pragma unroll
        for (int j = 0; j < 4; j++) aa[j] = As2[e][tx + 32*j];
#pragma unroll
        for (int i = 0; i < 7; i++)
#pragma unroll
            for (int j = 0; j < 4; j++) acc[i][j] += ga[i] * aa[j];
    }

    float* o = &d_simp[(size_t)(ch*2 + b2) * 100 * 100];
    for (int i = 0; i < nq; i++)
        for (int j = 0; j < nk; j++)
            o[(tx + 32*j)*100 + (ty + 16*i)] = acc[i][j];   // [k][q]
}

// ---------- Stage 5: reduce partials + softmax over q ----------
__global__ void __launch_bounds__(128) softmax_kernel(float* __restrict__ out)
{
    int k = blockIdx.x, b2 = blockIdx.y, t = threadIdx.x;
    __shared__ float wr[4];
    __shared__ float bval;
    const float rscale = 0.051031036307982884f;   // 1/sqrt(384)

    float v = -3.4e38f;
    if (t < 100) {
        float s = 0.0f;
#pragma unroll 6
        for (int ch = 0; ch < NCH; ch++)
            s += d_simp[(size_t)((ch*2 + b2)*100 + k)*100 + t];
        v = s * rscale;
    }

    float m = v;
#pragma unroll
    for (int off = 16; off > 0; off >>= 1)
        m = fmaxf(m, __shfl_down_sync(0xffffffffu, m, off));
    if ((t & 31) == 0) wr[t >> 5] = m;
    __syncthreads();
    if (t == 0) bval = fmaxf(fmaxf(wr[0], wr[1]), fmaxf(wr[2], wr[3]));
    __syncthreads();
    float mx = bval;

    float e = (t < 100) ? expf(v - mx) : 0.0f;
    float s = e;
#pragma unroll
    for (int off = 16; off > 0; off >>= 1)
        s += __shfl_down_sync(0xffffffffu, s, off);
    if ((t & 31) == 0) wr[t >> 5] = s;
    __syncthreads();
    if (t == 0) bval = wr[0] + wr[1] + wr[2] + wr[3];
    __syncthreads();

    if (t < 100)
        out[(b2*100 + t)*100 + k] = e / bval;
}

// ---------- launch ----------
extern "C" void kernel_launch(void* const* d_in, const int* in_sizes, int n_in,
                              void* d_out, int out_size)
{
    const float* g_samples = (const float*)d_in[0];
    const float* a_samples = (const float*)d_in[1];
    const float* g_logits  = (const float*)d_in[2];
    const float* a_logits  = (const float*)d_in[3];
    const float* g_boxes   = (const float*)d_in[4];
    const float* a_boxes   = (const float*)d_in[5];
    const float* W_ground  = (const float*)d_in[6];
    const float* W_aerial  = (const float*)d_in[7];
    const float* pos_enc   = (const float*)d_in[8];
    float* out = (float*)d_out;

    cudaFuncSetAttribute(hmma_gemm_kernel,
                         cudaFuncAttributeMaxDynamicSharedMemorySize, SMEM_GEMM_REQ);

    topk_kernel<<<dim3(2, 2), 1024>>>(g_logits, a_logits, g_boxes, a_boxes);
    roi_kernel<<<dim3(200, 2), 256>>>(g_samples, a_samples, pos_enc);
    hmma_gemm_kernel<<<dim3(43, 4, 2), 256, SMEM_GEMM_REQ>>>(W_ground, W_aerial);
    sim_kernel<<<dim3(NCH, 2), 512>>>();
    softmax_kernel<<<dim3(100, 2), 128>>>(out);
}

// round 15
// speedup vs baseline: 1.0695x; 1.0695x over previous
#include <cuda_runtime.h>
#include <cuda_bf16.h>
#include <cstdint>

#define IMG 1024
#define EMBED 2700
#define ECH 54            // sim e-chunk (50 chunks * 54 = 2700)
#define NCH 50

// device scratch (no cudaMalloc allowed)
__device__ float d_boxes_px[2 * 2 * 100 * 4];   // [view][batch][slot][xyxy px]
__device__ float d_t [2 * 200 * EMBED];         // [view][row][e]
__device__ float d_gt[2 * 200 * EMBED];         // after Linear
__device__ float d_simp[NCH * 2 * 100 * 100];   // partial sims [ch][b][k][q]

// ---------- Stage 1: top-100 via histogram select + small bitonic ----------
__device__ __forceinline__ unsigned int prob_key(float x) {
    float p = 1.0f / (1.0f + expf(-x));
    return __float_as_uint(p);
}

__global__ void __launch_bounds__(1024) topk_kernel(
    const float* __restrict__ gl, const float* __restrict__ al,
    const float* __restrict__ gbx, const float* __restrict__ abx)
{
    int b = blockIdx.x, v = blockIdx.y;
    const float* logits = (v ? al : gl) + b * 6000;
    const float* boxes  = (v ? abx : gbx) + b * 300 * 4;
    int tid = threadIdx.x;

    __shared__ unsigned int hist[256];
    __shared__ int sT, scnt;
    __shared__ unsigned long long cand[4096];

    if (tid < 256) hist[tid] = 0u;
    __syncthreads();

    for (int i = tid; i < 6000; i += 1024)
        atomicAdd(&hist[prob_key(logits[i]) >> 22], 1u);
    __syncthreads();

    if (tid == 0) {
        unsigned int cum = 0; int T = 0;
        for (int bb = 255; bb >= 0; bb--) {
            cum += hist[bb];
            if (cum >= 100u) { T = bb; break; }
        }
        sT = T; scnt = 0;
    }
    __syncthreads();
    int T = sT;

    for (int i = tid; i < 6000; i += 1024) {
        unsigned int key = prob_key(logits[i]);
        if ((int)(key >> 22) >= T) {
            int pos = atomicAdd(&scnt, 1);
            if (pos < 4096)
                cand[pos] = (((unsigned long long)(0xFFFFFFFFu ^ key)) << 16)
                            | (unsigned long long)i;
        }
    }
    __syncthreads();

    int n = min(scnt, 4096);
    int n2 = 128;
    while (n2 < n) n2 <<= 1;

    for (int i = n + tid; i < n2; i += 1024) cand[i] = ~0ull;
    __syncthreads();

    for (int k = 2; k <= n2; k <<= 1)
        for (int j = k >> 1; j > 0; j >>= 1) {
            for (int i = tid; i < n2; i += 1024) {
                int ixj = i ^ j;
                if (ixj > i) {
                    unsigned long long a = cand[i], bb2 = cand[ixj];
                    bool up = ((i & k) == 0);
                    if ((a > bb2) == up) { cand[i] = bb2; cand[ixj] = a; }
                }
            }
            __syncthreads();
        }

    if (tid < 100) {
        int idx = (int)(cand[tid] & 0xFFFFull);
        int q = idx / 20;
        float cx = boxes[q*4+0], cy = boxes[q*4+1];
        float w  = boxes[q*4+2], h  = boxes[q*4+3];
        float* o = &d_boxes_px[((v*2 + b)*100 + tid)*4];
        o[0] = (cx - 0.5f*w) * 1024.0f;  o[1] = (cy - 0.5f*h) * 1024.0f;
        o[2] = (cx + 0.5f*w) * 1024.0f;  o[3] = (cy + 0.5f*h) * 1024.0f;
    }
}

// ---------- Stage 2: ROI bilinear 30x30 + interleave + pos_enc ----------
__global__ void __launch_bounds__(256) roi_kernel(
    const float* __restrict__ g_img, const float* __restrict__ a_img,
    const float* __restrict__ pos_enc)
{
    int m = blockIdx.x, v = blockIdx.y;
    const float* img = v ? a_img : g_img;
    int b = m & 1, kslot = m >> 1, k2 = m % 100;
    int tid = threadIdx.x;

    const float* bx = &d_boxes_px[((v*2 + b)*100 + kslot)*4];
    float x0 = rintf(bx[0]), y0 = rintf(bx[1]);
    float x1 = rintf(bx[2]), y1 = rintf(bx[3]);
    float w = x1 - x0, h = y1 - y0;
    bool valid = (w > 0.0f) && (h > 0.0f);

    __shared__ int   iy0[30], iy1[30], ix0[30], ix1[30];
    __shared__ float fwy[30], fwx[30];
    if (tid < 30) {
        float g = (float)tid + 0.5f;
        float sy = fminf(fmaxf(g * h / 30.0f - 0.5f, 0.0f), fmaxf(h - 1.0f, 0.0f));
        float ay = y0 + sy, yf = floorf(ay);
        fwy[tid] = ay - yf;
        iy0[tid] = (int)fminf(fmaxf(yf,        0.0f), 1023.0f);
        iy1[tid] = (int)fminf(fmaxf(yf + 1.0f, 0.0f), 1023.0f);
        float sx = fminf(fmaxf(g * w / 30.0f - 0.5f, 0.0f), fmaxf(w - 1.0f, 0.0f));
        float ax = x0 + sx, xf = floorf(ax);
        fwx[tid] = ax - xf;
        ix0[tid] = (int)fminf(fmaxf(xf,        0.0f), 1023.0f);
        ix1[tid] = (int)fminf(fmaxf(xf + 1.0f, 0.0f), 1023.0f);
    }
    __syncthreads();

    float* trow = &d_t[((size_t)(v*200 + m)) * EMBED];
    const float* pe = &pos_enc[(size_t)k2 * EMBED];
    for (int e = tid; e < EMBED; e += 256) {
        float val = 0.0f;
        if (valid) {
            int c = e / 900, r = e - c*900, py = r / 30, px = r - py*30;
            const float* ip = img + ((size_t)(b*3 + c) << 20);
            float wy = fwy[py], wx = fwx[px];
            const float* r0p = ip + iy0[py]*IMG;
            const float* r1p = ip + iy1[py]*IMG;
            float v00 = r0p[ix0[px]], v01 = r0p[ix1[px]];
            float v10 = r1p[ix0[px]], v11 = r1p[ix1[px]];
            float top = v00*(1.0f-wx) + v01*wx;
            float bot = v10*(1.0f-wx) + v11*wx;
            val = top*(1.0f-wy) + bot*wy;
        }
        trow[e] = val + pe[e];
    }
}

// ---------- Stage 3: gt = t @ W^T via mma.sync bf16 hi/lo split ----------
// BM=96, BN=128, 384 thr (12 warps 3x4; warp tile 32x32). Best-measured shape.
#define KC 32
#define LDP 40   // padded row stride (bf16 elems): 80B -> conflict-free ldmatrix

__device__ __forceinline__ void ldm_x4(uint32_t& r0, uint32_t& r1, uint32_t& r2, uint32_t& r3,
                                       uint32_t addr) {
    asm volatile("ldmatrix.sync.aligned.m8n8.x4.shared.b16 {%0,%1,%2,%3}, [%4];"
                 : "=r"(r0), "=r"(r1), "=r"(r2), "=r"(r3) : "r"(addr));
}
__device__ __forceinline__ void ldm_x2(uint32_t& r0, uint32_t& r1, uint32_t addr) {
    asm volatile("ldmatrix.sync.aligned.m8n8.x2.shared.b16 {%0,%1}, [%2];"
                 : "=r"(r0), "=r"(r1) : "r"(addr));
}
__device__ __forceinline__ void mma_bf16(float* c, const uint32_t* a, const uint32_t* b) {
    asm volatile(
        "mma.sync.aligned.m16n8k16.row.col.f32.bf16.bf16.f32 "
        "{%0,%1,%2,%3}, {%4,%5,%6,%7}, {%8,%9}, {%0,%1,%2,%3};"
        : "+f"(c[0]), "+f"(c[1]), "+f"(c[2]), "+f"(c[3])
        : "r"(a[0]), "r"(a[1]), "r"(a[2]), "r"(a[3]), "r"(b[0]), "r"(b[1]));
}
__device__ __forceinline__ uint32_t smem_u32(const void* p) {
    uint32_t a;
    asm("{ .reg .u64 t; cvta.to.shared.u64 t, %1; cvt.u32.u64 %0, t; }" : "=r"(a) : "l"(p));
    return a;
}
__device__ __forceinline__ uint2 split4(float4 x) {
    __nv_bfloat16 h0 = __float2bfloat16(x.x), h1 = __float2bfloat16(x.y);
    __nv_bfloat16 h2 = __float2bfloat16(x.z), h3 = __float2bfloat16(x.w);
    __nv_bfloat162 a = __halves2bfloat162(h0, h1), b = __halves2bfloat162(h2, h3);
    return make_uint2(*(uint32_t*)&a, *(uint32_t*)&b);
}
__device__ __forceinline__ uint2 split4lo(float4 x) {
    __nv_bfloat16 h0 = __float2bfloat16(x.x), h1 = __float2bfloat16(x.y);
    __nv_bfloat16 h2 = __float2bfloat16(x.z), h3 = __float2bfloat16(x.w);
    __nv_bfloat16 l0 = __float2bfloat16(x.x - __bfloat162float(h0));
    __nv_bfloat16 l1 = __float2bfloat16(x.y - __bfloat162float(h1));
    __nv_bfloat16 l2 = __float2bfloat16(x.z - __bfloat162float(h2));
    __nv_bfloat16 l3 = __float2bfloat16(x.w - __bfloat162float(h3));
    __nv_bfloat162 a = __halves2bfloat162(l0, l1), b = __halves2bfloat162(l2, l3);
    return make_uint2(*(uint32_t*)&a, *(uint32_t*)&b);
}

__global__ void __launch_bounds__(384, 1) hmma_gemm_kernel(
    const float* __restrict__ Wg, const float* __restrict__ Wa)
{
    const int v = blockIdx.z;
    const int row0  = blockIdx.y * 96;
    const int ncol0 = blockIdx.x * 128;
    const float* __restrict__ A = d_t + (size_t)v * 200 * EMBED;
    const float* __restrict__ B = v ? Wa : Wg;
    float* __restrict__ C = d_gt + (size_t)v * 200 * EMBED;

    __shared__ __nv_bfloat16 Ah[96][LDP],  Al[96][LDP];
    __shared__ __nv_bfloat16 Bh[128][LDP], Bl[128][LDP];

    int tid = threadIdx.x;
    int wid = tid >> 5, lane = tid & 31;
    int wm = wid >> 2, wn = wid & 3;         // 3x4 warp grid

    bool imv0 = (row0 + wm * 32)      < 200;
    bool imv1 = (row0 + wm * 32 + 16) < 200;

    float acc[2][4][4];
#pragma unroll
    for (int i = 0; i < 2; i++)
#pragma unroll
        for (int j = 0; j < 4; j++)
#pragma unroll
            for (int p = 0; p < 4; p++) acc[i][j][p] = 0.0f;

    float4 aPre[2], bPre[3];

    auto loadTile = [&](int c) {
        int k0 = c * KC;
#pragma unroll
        for (int l = 0; l < 2; l++) {
            int g = tid + l * 384;
            int r = g >> 3, c4 = g & 7;
            int gr = row0 + r, gc = k0 + c4 * 4;
            float4 x = make_float4(0.f, 0.f, 0.f, 0.f);
            if (gr < 200 && gc < EMBED) x = *(const float4*)(A + (size_t)gr * EMBED + gc);
            aPre[l] = x;
        }
#pragma unroll
        for (int l = 0; l < 3; l++) {
            int g = tid + l * 384;
            float4 y = make_float4(0.f, 0.f, 0.f, 0.f);
            if (g < 1024) {
                int r = g >> 3, c4 = g & 7;
                int gr2 = ncol0 + r, gc = k0 + c4 * 4;
                if (gr2 < EMBED && gc < EMBED)
                    y = *(const float4*)(B + (size_t)gr2 * EMBED + gc);
            }
            bPre[l] = y;
        }
    };
    auto storeTile = [&]() {
#pragma unroll
        for (int l = 0; l < 2; l++) {
            int g = tid + l * 384;
            int r = g >> 3, c4 = g & 7;
            *(uint2*)&Ah[r][c4 * 4] = split4(aPre[l]);
            *(uint2*)&Al[r][c4 * 4] = split4lo(aPre[l]);
        }
#pragma unroll
        for (int l = 0; l < 3; l++) {
            int g = tid + l * 384;
            if (g < 1024) {
                int r = g >> 3, c4 = g & 7;
                *(uint2*)&Bh[r][c4 * 4] = split4(bPre[l]);
                *(uint2*)&Bl[r][c4 * 4] = split4lo(bPre[l]);
            }
        }
    };

    uint32_t sAh = smem_u32(Ah), sAl = smem_u32(Al);
    uint32_t sBh = smem_u32(Bh), sBl = smem_u32(Bl);

    const int NCHK = (EMBED + KC - 1) / KC;   // 85
    loadTile(0); storeTile(); __syncthreads();

    for (int c = 0; c < NCHK; c++) {
        if (c + 1 < NCHK) loadTile(c + 1);

        if (imv0 || imv1) {
#pragma unroll
            for (int ks = 0; ks < 2; ks++) {
                int k0 = ks * 16;
                int sub = lane >> 3, ri = lane & 7;
                uint32_t ah[2][4], al[2][4], bh[4][2], bl[4][2];
#pragma unroll
                for (int jn = 0; jn < 4; jn++) {
                    int n0 = wn * 32 + jn * 8;
                    uint32_t off = ((uint32_t)((n0 + ri) * LDP + k0 + sub * 8)) * 2;
                    ldm_x2(bh[jn][0], bh[jn][1], sBh + off);
                    ldm_x2(bl[jn][0], bl[jn][1], sBl + off);
                }
#pragma unroll
                for (int im = 0; im < 2; im++) {
                    if (!(im ? imv1 : imv0)) continue;
                    int m0 = wm * 32 + im * 16;
                    uint32_t off = ((uint32_t)((m0 + (sub & 1) * 8 + ri) * LDP
                                               + k0 + (sub >> 1) * 8)) * 2;
                    ldm_x4(ah[im][0], ah[im][1], ah[im][2], ah[im][3], sAh + off);
                    ldm_x4(al[im][0], al[im][1], al[im][2], al[im][3], sAl + off);
#pragma unroll
                    for (int jn = 0; jn < 4; jn++) {
                        mma_bf16(acc[im][jn], ah[im], bh[jn]);
                        mma_bf16(acc[im][jn], ah[im], bl[jn]);
                        mma_bf16(acc[im][jn], al[im], bh[jn]);
                    }
                }
            }
        }
        __syncthreads();
        if (c + 1 < NCHK) { storeTile(); __syncthreads(); }
    }

#pragma unroll
    for (int im = 0; im < 2; im++) {
        if (!(im ? imv1 : imv0)) continue;
        int mbase = row0 + wm * 32 + im * 16 + (lane >> 2);
#pragma unroll
        for (int jn = 0; jn < 4; jn++) {
            int n = ncol0 + wn * 32 + jn * 8 + (lane & 3) * 2;
            if (n < EMBED) {
                if (mbase < 200)
                    *(float2*)(C + (size_t)mbase * EMBED + n) =
                        make_float2(acc[im][jn][0], acc[im][jn][1]);
                if (mbase + 8 < 200)
                    *(float2*)(C + (size_t)(mbase + 8) * EMBED + n) =
                        make_float2(acc[im][jn][2], acc[im][jn][3]);
            }
        }
    }
}

// ---------- Stage 4: sim partials (best-measured variant: 256 thr, ECH=54) ----------
__global__ void __launch_bounds__(256) sim_kernel()
{
    int ch = blockIdx.x, b2 = blockIdx.y;
    __shared__ float Gs [ECH][112];
    __shared__ float As2[ECH][112];

    int tid = threadIdx.x;
    int e0 = ch * ECH;
    for (int l = tid; l < 100 * ECH; l += 256) {
        int r = l / ECH, e = l - r * ECH;
        Gs [e][r] = d_gt[(size_t)(      b2*100 + r)*EMBED + e0 + e];
        As2[e][r] = d_gt[(size_t)(200 + b2*100 + r)*EMBED + e0 + e];
    }
    __syncthreads();

    int tx = tid & 15, ty = tid >> 4;
    int nq = (ty < 4) ? 7 : 6;
    int nk = (tx < 4) ? 7 : 6;

    float acc[7][7];
#pragma unroll
    for (int i = 0; i < 7; i++)
#pragma unroll
        for (int j = 0; j < 7; j++) acc[i][j] = 0.0f;

    for (int e = 0; e < ECH; e++) {
        float ga[7], aa[7];
#pragma unroll
        for (int i = 0; i < 7; i++) ga[i] = Gs [e][ty + 16*i];   // <=111 in-bounds
#pragma unroll
        for (int j = 0; j < 7; j++) aa[j] = As2[e][tx + 16*j];
#pragma unroll
        for (int i = 0; i < 7; i++)
#pragma unroll
            for (int j = 0; j < 7; j++) acc[i][j] += ga[i] * aa[j];
    }

    float* o = &d_simp[(size_t)(ch*2 + b2) * 100 * 100];
    for (int i = 0; i < nq; i++)
        for (int j = 0; j < nk; j++)
            o[(tx + 16*j)*100 + (ty + 16*i)] = acc[i][j];   // [k][q]
}

// ---------- Stage 5: reduce partials + softmax over q ----------
__global__ void __launch_bounds__(128) softmax_kernel(float* __restrict__ out)
{
    int k = blockIdx.x, b2 = blockIdx.y, t = threadIdx.x;
    __shared__ float wr[4];
    __shared__ float bval;
    const float rscale = 0.051031036307982884f;   // 1/sqrt(384)

    float v = -3.4e38f;
    if (t < 100) {
        float s = 0.0f;
#pragma unroll 5
        for (int ch = 0; ch < NCH; ch++)
            s += d_simp[(size_t)((ch*2 + b2)*100 + k)*100 + t];
        v = s * rscale;
    }

    float m = v;
#pragma unroll
    for (int off = 16; off > 0; off >>= 1)
        m = fmaxf(m, __shfl_down_sync(0xffffffffu, m, off));
    if ((t & 31) == 0) wr[t >> 5] = m;
    __syncthreads();
    if (t == 0) bval = fmaxf(fmaxf(wr[0], wr[1]), fmaxf(wr[2], wr[3]));
    __syncthreads();
    float mx = bval;

    float e = (t < 100) ? expf(v - mx) : 0.0f;
    float s = e;
#pragma unroll
    for (int off = 16; off > 0; off >>= 1)
        s += __shfl_down_sync(0xffffffffu, s, off);
    if ((t & 31) == 0) wr[t >> 5] = s;
    __syncthreads();
    if (t == 0) bval = wr[0] + wr[1] + wr[2] + wr[3];
    __syncthreads();

    if (t < 100)
        out[(b2*100 + t)*100 + k] = e / bval;
}

// ---------- launch ----------
extern "C" void kernel_launch(void* const* d_in, const int* in_sizes, int n_in,
                              void* d_out, int out_size)
{
    const float* g_samples = (const float*)d_in[0];
    const float* a_samples = (const float*)d_in[1];
    const float* g_logits  = (const float*)d_in[2];
    const float* a_logits  = (const float*)d_in[3];
    const float* g_boxes   = (const float*)d_in[4];
    const float* a_boxes   = (const float*)d_in[5];
    const float* W_ground  = (const float*)d_in[6];
    const float* W_aerial  = (const float*)d_in[7];
    const float* pos_enc   = (const float*)d_in[8];
    float* out = (float*)d_out;

    topk_kernel<<<dim3(2, 2), 1024>>>(g_logits, a_logits, g_boxes, a_boxes);
    roi_kernel<<<dim3(200, 2), 256>>>(g_samples, a_samples, pos_enc);
    hmma_gemm_kernel<<<dim3(22, 3, 2), 384>>>(W_ground, W_aerial);
    sim_kernel<<<dim3(NCH, 2), 256>>>();
    softmax_kernel<<<dim3(100, 2), 128>>>(out);
}

// round 16
// speedup vs baseline: 1.3184x; 1.2327x over previous
#include <cuda_runtime.h>
#include <cuda_bf16.h>
#include <cstdint>

#define IMG 1024
#define EMBED 2700
#define ECH 54            // sim e-chunk (50 chunks * 54 = 2700)
#define NCH 50

// device scratch (no cudaMalloc allowed)
__device__ float d_boxes_px[2 * 2 * 100 * 4];   // [view][batch][slot][xyxy px]
__device__ float d_t [2 * 200 * EMBED];         // [view][row][e]
__device__ float d_gt[2 * 200 * EMBED];         // after Linear
__device__ float d_simp[NCH * 2 * 100 * 100];   // partial sims [ch][b][k][q]

// ---------- Stage 1: top-100 via histogram select + small bitonic ----------
__device__ __forceinline__ unsigned int prob_key(float x) {
    float p = 1.0f / (1.0f + expf(-x));
    return __float_as_uint(p);
}

__global__ void __launch_bounds__(1024) topk_kernel(
    const float* __restrict__ gl, const float* __restrict__ al,
    const float* __restrict__ gbx, const float* __restrict__ abx)
{
    int b = blockIdx.x, v = blockIdx.y;
    const float* logits = (v ? al : gl) + b * 6000;
    const float* boxes  = (v ? abx : gbx) + b * 300 * 4;
    int tid = threadIdx.x;

    __shared__ unsigned int hist[256];
    __shared__ int sT, scnt;
    __shared__ unsigned long long cand[4096];

    if (tid < 256) hist[tid] = 0u;
    __syncthreads();

    for (int i = tid; i < 6000; i += 1024)
        atomicAdd(&hist[prob_key(logits[i]) >> 22], 1u);
    __syncthreads();

    if (tid == 0) {
        unsigned int cum = 0; int T = 0;
        for (int bb = 255; bb >= 0; bb--) {
            cum += hist[bb];
            if (cum >= 100u) { T = bb; break; }
        }
        sT = T; scnt = 0;
    }
    __syncthreads();
    int T = sT;

    for (int i = tid; i < 6000; i += 1024) {
        unsigned int key = prob_key(logits[i]);
        if ((int)(key >> 22) >= T) {
            int pos = atomicAdd(&scnt, 1);
            if (pos < 4096)
                cand[pos] = (((unsigned long long)(0xFFFFFFFFu ^ key)) << 16)
                            | (unsigned long long)i;
        }
    }
    __syncthreads();

    int n = min(scnt, 4096);
    int n2 = 128;
    while (n2 < n) n2 <<= 1;

    for (int i = n + tid; i < n2; i += 1024) cand[i] = ~0ull;
    __syncthreads();

    for (int k = 2; k <= n2; k <<= 1)
        for (int j = k >> 1; j > 0; j >>= 1) {
            for (int i = tid; i < n2; i += 1024) {
                int ixj = i ^ j;
                if (ixj > i) {
                    unsigned long long a = cand[i], bb2 = cand[ixj];
                    bool up = ((i & k) == 0);
                    if ((a > bb2) == up) { cand[i] = bb2; cand[ixj] = a; }
                }
            }
            __syncthreads();
        }

    if (tid < 100) {
        int idx = (int)(cand[tid] & 0xFFFFull);
        int q = idx / 20;
        float cx = boxes[q*4+0], cy = boxes[q*4+1];
        float w  = boxes[q*4+2], h  = boxes[q*4+3];
        float* o = &d_boxes_px[((v*2 + b)*100 + tid)*4];
        o[0] = (cx - 0.5f*w) * 1024.0f;  o[1] = (cy - 0.5f*h) * 1024.0f;
        o[2] = (cx + 0.5f*w) * 1024.0f;  o[3] = (cy + 0.5f*h) * 1024.0f;
    }
}

// ---------- Stage 2: ROI bilinear 30x30 + interleave + pos_enc ----------
__global__ void __launch_bounds__(256) roi_kernel(
    const float* __restrict__ g_img, const float* __restrict__ a_img,
    const float* __restrict__ pos_enc)
{
    int m = blockIdx.x, v = blockIdx.y;
    const float* img = v ? a_img : g_img;
    int b = m & 1, kslot = m >> 1, k2 = m % 100;
    int tid = threadIdx.x;

    const float* bx = &d_boxes_px[((v*2 + b)*100 + kslot)*4];
    float x0 = rintf(bx[0]), y0 = rintf(bx[1]);
    float x1 = rintf(bx[2]), y1 = rintf(bx[3]);
    float w = x1 - x0, h = y1 - y0;
    bool valid = (w > 0.0f) && (h > 0.0f);

    __shared__ int   iy0[30], iy1[30], ix0[30], ix1[30];
    __shared__ float fwy[30], fwx[30];
    if (tid < 30) {
        float g = (float)tid + 0.5f;
        float sy = fminf(fmaxf(g * h / 30.0f - 0.5f, 0.0f), fmaxf(h - 1.0f, 0.0f));
        float ay = y0 + sy, yf = floorf(ay);
        fwy[tid] = ay - yf;
        iy0[tid] = (int)fminf(fmaxf(yf,        0.0f), 1023.0f);
        iy1[tid] = (int)fminf(fmaxf(yf + 1.0f, 0.0f), 1023.0f);
        float sx = fminf(fmaxf(g * w / 30.0f - 0.5f, 0.0f), fmaxf(w - 1.0f, 0.0f));
        float ax = x0 + sx, xf = floorf(ax);
        fwx[tid] = ax - xf;
        ix0[tid] = (int)fminf(fmaxf(xf,        0.0f), 1023.0f);
        ix1[tid] = (int)fminf(fmaxf(xf + 1.0f, 0.0f), 1023.0f);
    }
    __syncthreads();

    float* trow = &d_t[((size_t)(v*200 + m)) * EMBED];
    const float* pe = &pos_enc[(size_t)k2 * EMBED];
    for (int e = tid; e < EMBED; e += 256) {
        float val = 0.0f;
        if (valid) {
            int c = e / 900, r = e - c*900, py = r / 30, px = r - py*30;
            const float* ip = img + ((size_t)(b*3 + c) << 20);
            float wy = fwy[py], wx = fwx[px];
            const float* r0p = ip + iy0[py]*IMG;
            const float* r1p = ip + iy1[py]*IMG;
            float v00 = r0p[ix0[px]], v01 = r0p[ix1[px]];
            float v10 = r1p[ix0[px]], v11 = r1p[ix1[px]];
            float top = v00*(1.0f-wx) + v01*wx;
            float bot = v10*(1.0f-wx) + v11*wx;
            val = top*(1.0f-wy) + bot*wy;
        }
        trow[e] = val + pe[e];
    }
}

// ---------- Stage 3: gt = t @ W^T via mma.sync bf16 hi/lo split ----------
// BM=96, BN=128, 384 thr (12 warps 3x4; warp tile 32x32). KC=64 (43 chunks,
// half the barriers) + B ldmatrix.x4 merge (32 vs 48 ldmatrix per 64-K).
#define KC 64
#define LDP 72   // padded row stride (bf16): 144B -> 8-row phases distinct, conflict-free
#define A_BYTES (96 * LDP * 2)               // 13824
#define B_BYTES (128 * LDP * 2)              // 18432
#define SMEM_GEMM (2*A_BYTES + 2*B_BYTES)    // 64512

__device__ __forceinline__ void ldm_x4(uint32_t& r0, uint32_t& r1, uint32_t& r2, uint32_t& r3,
                                       uint32_t addr) {
    asm volatile("ldmatrix.sync.aligned.m8n8.x4.shared.b16 {%0,%1,%2,%3}, [%4];"
                 : "=r"(r0), "=r"(r1), "=r"(r2), "=r"(r3) : "r"(addr));
}
__device__ __forceinline__ void mma_bf16(float* c, const uint32_t* a, const uint32_t* b) {
    asm volatile(
        "mma.sync.aligned.m16n8k16.row.col.f32.bf16.bf16.f32 "
        "{%0,%1,%2,%3}, {%4,%5,%6,%7}, {%8,%9}, {%0,%1,%2,%3};"
        : "+f"(c[0]), "+f"(c[1]), "+f"(c[2]), "+f"(c[3])
        : "r"(a[0]), "r"(a[1]), "r"(a[2]), "r"(a[3]), "r"(b[0]), "r"(b[1]));
}
__device__ __forceinline__ uint32_t smem_u32(const void* p) {
    uint32_t a;
    asm("{ .reg .u64 t; cvta.to.shared.u64 t, %1; cvt.u32.u64 %0, t; }" : "=r"(a) : "l"(p));
    return a;
}
__device__ __forceinline__ uint2 split4(float4 x) {
    __nv_bfloat16 h0 = __float2bfloat16(x.x), h1 = __float2bfloat16(x.y);
    __nv_bfloat16 h2 = __float2bfloat16(x.z), h3 = __float2bfloat16(x.w);
    __nv_bfloat162 a = __halves2bfloat162(h0, h1), b = __halves2bfloat162(h2, h3);
    return make_uint2(*(uint32_t*)&a, *(uint32_t*)&b);
}
__device__ __forceinline__ uint2 split4lo(float4 x) {
    __nv_bfloat16 h0 = __float2bfloat16(x.x), h1 = __float2bfloat16(x.y);
    __nv_bfloat16 h2 = __float2bfloat16(x.z), h3 = __float2bfloat16(x.w);
    __nv_bfloat16 l0 = __float2bfloat16(x.x - __bfloat162float(h0));
    __nv_bfloat16 l1 = __float2bfloat16(x.y - __bfloat162float(h1));
    __nv_bfloat16 l2 = __float2bfloat16(x.z - __bfloat162float(h2));
    __nv_bfloat16 l3 = __float2bfloat16(x.w - __bfloat162float(h3));
    __nv_bfloat162 a = __halves2bfloat162(l0, l1), b = __halves2bfloat162(l2, l3);
    return make_uint2(*(uint32_t*)&a, *(uint32_t*)&b);
}

__global__ void __launch_bounds__(384, 1) hmma_gemm_kernel(
    const float* __restrict__ Wg, const float* __restrict__ Wa)
{
    extern __shared__ char smraw[];
    const int v = blockIdx.z;
    const int row0  = blockIdx.y * 96;
    const int ncol0 = blockIdx.x * 128;
    const float* __restrict__ A = d_t + (size_t)v * 200 * EMBED;
    const float* __restrict__ B = v ? Wa : Wg;
    float* __restrict__ C = d_gt + (size_t)v * 200 * EMBED;

    char* pAh = smraw;
    char* pAl = smraw + A_BYTES;
    char* pBh = smraw + 2*A_BYTES;
    char* pBl = smraw + 2*A_BYTES + B_BYTES;

    int tid = threadIdx.x;
    int wid = tid >> 5, lane = tid & 31;
    int wm = wid >> 2, wn = wid & 3;         // 3x4 warp grid, warp tile 32x32

    bool imv0 = (row0 + wm * 32)      < 200;
    bool imv1 = (row0 + wm * 32 + 16) < 200;

    float acc[2][4][4];
#pragma unroll
    for (int i = 0; i < 2; i++)
#pragma unroll
        for (int j = 0; j < 4; j++)
#pragma unroll
            for (int p = 0; p < 4; p++) acc[i][j][p] = 0.0f;

    float4 aPre[4], bPre[6];

    auto loadTile = [&](int c) {
        int k0 = c * KC;
        // A: 96 x 64 = 1536 float4 over 384 thr (4 each)
#pragma unroll
        for (int l = 0; l < 4; l++) {
            int g = tid + l * 384;
            int r = g >> 4, c4 = g & 15;
            int gr = row0 + r, gc = k0 + c4 * 4;
            float4 x = make_float4(0.f, 0.f, 0.f, 0.f);
            if (gr < 200 && gc < EMBED) x = *(const float4*)(A + (size_t)gr * EMBED + gc);
            aPre[l] = x;
        }
        // B: 128 x 64 = 2048 float4 over 384 thr (6 rounds, last partial)
#pragma unroll
        for (int l = 0; l < 6; l++) {
            int g = tid + l * 384;
            float4 y = make_float4(0.f, 0.f, 0.f, 0.f);
            if (g < 2048) {
                int r = g >> 4, c4 = g & 15;
                int gr2 = ncol0 + r, gc = k0 + c4 * 4;
                if (gr2 < EMBED && gc < EMBED)
                    y = *(const float4*)(B + (size_t)gr2 * EMBED + gc);
            }
            bPre[l] = y;
        }
    };
    auto storeTile = [&]() {
#pragma unroll
        for (int l = 0; l < 4; l++) {
            int g = tid + l * 384;
            int r = g >> 4, c4 = g & 15;
            uint32_t off = (uint32_t)(r * LDP + c4 * 4) * 2;
            *(uint2*)(pAh + off) = split4(aPre[l]);
            *(uint2*)(pAl + off) = split4lo(aPre[l]);
        }
#pragma unroll
        for (int l = 0; l < 6; l++) {
            int g = tid + l * 384;
            if (g < 2048) {
                int r = g >> 4, c4 = g & 15;
                uint32_t off = (uint32_t)(r * LDP + c4 * 4) * 2;
                *(uint2*)(pBh + off) = split4(bPre[l]);
                *(uint2*)(pBl + off) = split4lo(bPre[l]);
            }
        }
    };

    uint32_t sAh = smem_u32(pAh), sAl = smem_u32(pAl);
    uint32_t sBh = smem_u32(pBh), sBl = smem_u32(pBl);

    const int NCHK = (EMBED + KC - 1) / KC;   // 43
    loadTile(0); storeTile(); __syncthreads();

    for (int c = 0; c < NCHK; c++) {
        if (c + 1 < NCHK) loadTile(c + 1);

        if (imv0 || imv1) {
#pragma unroll
            for (int ks = 0; ks < 4; ks++) {
                int k0 = ks * 16;
                int sub = lane >> 3, ri = lane & 7;
                uint32_t ah[2][4], al[2][4], bh[4][2], bl[4][2];
                // B: x4 merge — lanes 0-7:(jn,k0) 8-15:(jn,k0+8) 16-23:(jn+1,k0) 24-31:(jn+1,k0+8)
#pragma unroll
                for (int jp = 0; jp < 2; jp++) {
                    int n0 = wn * 32 + jp * 16;                 // frags jn=2*jp, 2*jp+1
                    int nrow = n0 + (sub >> 1) * 8 + ri;        // sub>=2 -> second n-frag
                    int kcol = k0 + (sub & 1) * 8;
                    uint32_t off = ((uint32_t)(nrow * LDP + kcol)) * 2;
                    ldm_x4(bh[2*jp][0], bh[2*jp][1], bh[2*jp+1][0], bh[2*jp+1][1], sBh + off);
                    ldm_x4(bl[2*jp][0], bl[2*jp][1], bl[2*jp+1][0], bl[2*jp+1][1], sBl + off);
                }
#pragma unroll
                for (int im = 0; im < 2; im++) {
                    if (!(im ? imv1 : imv0)) continue;
                    int m0 = wm * 32 + im * 16;
                    uint32_t off = ((uint32_t)((m0 + (sub & 1) * 8 + ri) * LDP
                                               + k0 + (sub >> 1) * 8)) * 2;
                    ldm_x4(ah[im][0], ah[im][1], ah[im][2], ah[im][3], sAh + off);
                    ldm_x4(al[im][0], al[im][1], al[im][2], al[im][3], sAl + off);
#pragma unroll
                    for (int jn = 0; jn < 4; jn++) {
                        mma_bf16(acc[im][jn], ah[im], bh[jn]);
                        mma_bf16(acc[im][jn], ah[im], bl[jn]);
                        mma_bf16(acc[im][jn], al[im], bh[jn]);
                    }
                }
            }
        }
        __syncthreads();
        if (c + 1 < NCHK) { storeTile(); __syncthreads(); }
    }

#pragma unroll
    for (int im = 0; im < 2; im++) {
        if (!(im ? imv1 : imv0)) continue;
        int mbase = row0 + wm * 32 + im * 16 + (lane >> 2);
#pragma unroll
        for (int jn = 0; jn < 4; jn++) {
            int n = ncol0 + wn * 32 + jn * 8 + (lane & 3) * 2;
            if (n < EMBED) {
                if (mbase < 200)
                    *(float2*)(C + (size_t)mbase * EMBED + n) =
                        make_float2(acc[im][jn][0], acc[im][jn][1]);
                if (mbase + 8 < 200)
                    *(float2*)(C + (size_t)(mbase + 8) * EMBED + n) =
                        make_float2(acc[im][jn][2], acc[im][jn][3]);
            }
        }
    }
}

// ---------- Stage 4: sim partials (best-measured: 256 thr, ECH=54) ----------
__global__ void __launch_bounds__(256) sim_kernel()
{
    int ch = blockIdx.x, b2 = blockIdx.y;
    __shared__ float Gs [ECH][112];
    __shared__ float As2[ECH][112];

    int tid = threadIdx.x;
    int e0 = ch * ECH;
    for (int l = tid; l < 100 * ECH; l += 256) {
        int r = l / ECH, e = l - r * ECH;
        Gs [e][r] = d_gt[(size_t)(      b2*100 + r)*EMBED + e0 + e];
        As2[e][r] = d_gt[(size_t)(200 + b2*100 + r)*EMBED + e0 + e];
    }
    __syncthreads();

    int tx = tid & 15, ty = tid >> 4;
    int nq = (ty < 4) ? 7 : 6;
    int nk = (tx < 4) ? 7 : 6;

    float acc[7][7];
#pragma unroll
    for (int i = 0; i < 7; i++)
#pragma unroll
        for (int j = 0; j < 7; j++) acc[i][j] = 0.0f;

    for (int e = 0; e < ECH; e++) {
        float ga[7], aa[7];
#pragma unroll
        for (int i = 0; i < 7; i++) ga[i] = Gs [e][ty + 16*i];   // <=111 in-bounds
#pragma unroll
        for (int j = 0; j < 7; j++) aa[j] = As2[e][tx + 16*j];
#pragma unroll
        for (int i = 0; i < 7; i++)
#pragma unroll
            for (int j = 0; j < 7; j++) acc[i][j] += ga[i] * aa[j];
    }

    float* o = &d_simp[(size_t)(ch*2 + b2) * 100 * 100];
    for (int i = 0; i < nq; i++)
        for (int j = 0; j < nk; j++)
            o[(tx + 16*j)*100 + (ty + 16*i)] = acc[i][j];   // [k][q]
}

// ---------- Stage 5: reduce partials + softmax over q ----------
__global__ void __launch_bounds__(128) softmax_kernel(float* __restrict__ out)
{
    int k = blockIdx.x, b2 = blockIdx.y, t = threadIdx.x;
    __shared__ float wr[4];
    __shared__ float bval;
    const float rscale = 0.051031036307982884f;   // 1/sqrt(384)

    float v = -3.4e38f;
    if (t < 100) {
        float s = 0.0f;
#pragma unroll 5
        for (int ch = 0; ch < NCH; ch++)
            s += d_simp[(size_t)((ch*2 + b2)*100 + k)*100 + t];
        v = s * rscale;
    }

    float m = v;
#pragma unroll
    for (int off = 16; off > 0; off >>= 1)
        m = fmaxf(m, __shfl_down_sync(0xffffffffu, m, off));
    if ((t & 31) == 0) wr[t >> 5] = m;
    __syncthreads();
    if (t == 0) bval = fmaxf(fmaxf(wr[0], wr[1]), fmaxf(wr[2], wr[3]));
    __syncthreads();
    float mx = bval;

    float e = (t < 100) ? expf(v - mx) : 0.0f;
    float s = e;
#pragma unroll
    for (int off = 16; off > 0; off >>= 1)
        s += __shfl_down_sync(0xffffffffu, s, off);
    if ((t & 31) == 0) wr[t >> 5] = s;
    __syncthreads();
    if (t == 0) bval = wr[0] + wr[1] + wr[2] + wr[3];
    __syncthreads();

    if (t < 100)
        out[(b2*100 + t)*100 + k] = e / bval;
}

// ---------- launch ----------
extern "C" void kernel_launch(void* const* d_in, const int* in_sizes, int n_in,
                              void* d_out, int out_size)
{
    const float* g_samples = (const float*)d_in[0];
    const float* a_samples = (const float*)d_in[1];
    const float* g_logits  = (const float*)d_in[2];
    const float* a_logits  = (const float*)d_in[3];
    const float* g_boxes   = (const float*)d_in[4];
    const float* a_boxes   = (const float*)d_in[5];
    const float* W_ground  = (const float*)d_in[6];
    const float* W_aerial  = (const float*)d_in[7];
    const float* pos_enc   = (const float*)d_in[8];
    float* out = (float*)d_out;

    cudaFuncSetAttribute(hmma_gemm_kernel,
                         cudaFuncAttributeMaxDynamicSharedMemorySize, SMEM_GEMM);

    topk_kernel<<<dim3(2, 2), 1024>>>(g_logits, a_logits, g_boxes, a_boxes);
    roi_kernel<<<dim3(200, 2), 256>>>(g_samples, a_samples, pos_enc);
    hmma_gemm_kernel<<<dim3(22, 3, 2), 384, SMEM_GEMM>>>(W_ground, W_aerial);
    sim_kernel<<<dim3(NCH, 2), 256>>>();
    softmax_kernel<<<dim3(100, 2), 128>>>(out);
}